// round 9
// baseline (speedup 1.0000x reference)
#include <cuda_runtime.h>

// VectorQuantizer: argmax_k ( W[k] . z ), emit W[argmax], index, commit loss.
// W: 131072 x 1024 f32 (512 MiB) -> HBM wall (~7.3 TB/s) reached by the
// streaming loop; remaining cost was the 2nd launch + finalize exposure.
// SINGLE kernel, block-specialized: block 0 = dedicated finalizer (prefetch z,
// spin on done-counter, epilogue overlaps the streaming drain); blocks
// 1..2048 = untouched best streaming body, NO reg cap (ptxas free).

#define VQ_DIM   1024
#define VQ_ROWS  131072
#define ARG_BLOCKS  2048                 // streaming blocks (grid = 2049)
#define ARG_THREADS 256
#define N_WARPS_TOT (ARG_BLOCKS * ARG_THREADS / 32)   // 16384 -> 8 rows/warp

// Per-block packed (float_key(dot) << 32 | ~row). Overwritten every launch.
__device__ unsigned long long g_block_best[ARG_BLOCKS];
__device__ unsigned int g_done_count = 0;   // finalizer resets each replay

// Monotonic float -> uint key: preserves ordering for all finite floats.
__device__ __forceinline__ unsigned float_key(float f) {
    unsigned u = __float_as_uint(f);
    return (u & 0x80000000u) ? ~u : (u | 0x80000000u);
}

__global__ __launch_bounds__(ARG_THREADS, 2)   // loose: ptxas freedom on hot path
void vq_kernel(const float* __restrict__ z, const float* __restrict__ W,
               float* __restrict__ out, int out_size) {
    __shared__ float zs[VQ_DIM];
    __shared__ unsigned long long red64[ARG_THREADS / 32];

    const int tid  = threadIdx.x;
    const int lane = tid & 31;
    const int wwid = tid >> 5;

    if (blockIdx.x == 0) {
        // ================= Finalizer block =================
        __shared__ float redf[ARG_THREADS / 32];

        // Prefetch z into registers while the streaming grid runs.
        float zv0 = z[tid];
        float zv1 = z[tid + 256];
        float zv2 = z[tid + 512];
        float zv3 = z[tid + 768];

        // Wait until all 2048 streaming blocks have PUBLISHED their slots
        // (release-fenced counter), not until they have retired.
        if (tid == 0) {
            unsigned c;
            do {
                __nanosleep(128);
                asm volatile("ld.acquire.gpu.u32 %0, [%1];"
                             : "=r"(c) : "l"(&g_done_count));
            } while (c < ARG_BLOCKS);
        }
        __syncthreads();
        __threadfence();   // acquire: slot stores visible

        // Scan 2048 slots, 8 per thread (L2-hot).
        unsigned long long b = 0ULL;
        #pragma unroll
        for (int j = 0; j < ARG_BLOCKS / ARG_THREADS; j++) {
            unsigned long long v = g_block_best[tid + j * ARG_THREADS];
            if (v > b) b = v;
        }
        #pragma unroll
        for (int off = 16; off; off >>= 1) {
            unsigned long long o = __shfl_xor_sync(0xffffffffu, b, off);
            if (o > b) b = o;
        }
        if (lane == 0) red64[wwid] = b;
        __syncthreads();
        if (tid == 0) {
            unsigned long long v = red64[0];
            #pragma unroll
            for (int i = 1; i < ARG_THREADS / 32; i++)
                if (red64[i] > v) v = red64[i];
            red64[0] = v;
        }
        __syncthreads();
        const unsigned row = 0xFFFFFFFFu - (unsigned)(red64[0] & 0xFFFFFFFFull);
        const float* q = W + (size_t)row * VQ_DIM;

        // Copy winning row + commitment loss (4 elems/thread).
        float q0 = q[tid];
        float q1 = q[tid + 256];
        float q2 = q[tid + 512];
        float q3 = q[tid + 768];
        if (tid       < out_size) out[tid]       = q0;
        if (tid + 256 < out_size) out[tid + 256] = q1;
        if (tid + 512 < out_size) out[tid + 512] = q2;
        if (tid + 768 < out_size) out[tid + 768] = q3;
        float d0 = zv0 - q0, d1 = zv1 - q1, d2 = zv2 - q2, d3 = zv3 - q3;
        float s = d0 * d0 + d1 * d1 + d2 * d2 + d3 * d3;
        #pragma unroll
        for (int off = 16; off; off >>= 1)
            s += __shfl_xor_sync(0xffffffffu, s, off);
        if (lane == 0) redf[wwid] = s;
        __syncthreads();
        if (tid == 0) {
            float t = 0.f;
            #pragma unroll
            for (int i = 0; i < ARG_THREADS / 32; i++) t += redf[i];
            if (out_size >= VQ_DIM + 1) out[VQ_DIM]     = (float)row;
            if (out_size >= VQ_DIM + 2) out[VQ_DIM + 1] = 0.25f * t / (float)VQ_DIM;
            __threadfence();
            g_done_count = 0;   // reset for next graph replay
        }
        return;
    }

    // ================= Streaming blocks (1..2048) =================
    // Stage z into shared (4 KB), vectorized.
    const float4* z4 = (const float4*)z;
    float4* zs4 = (float4*)zs;
    for (int i = tid; i < VQ_DIM / 4; i += ARG_THREADS)
        zs4[i] = z4[i];
    __syncthreads();

    const int gwarp = ((blockIdx.x - 1) * ARG_THREADS + tid) >> 5;

    unsigned long long best = 0ULL;

    for (int row = gwarp; row < VQ_ROWS; row += N_WARPS_TOT) {
        const float4* wr = (const float4*)(W + (size_t)row * VQ_DIM);
        // Fastest measured body: 4 accumulators, two 4-deep batches.
        float a0 = 0.f, a1 = 0.f, a2 = 0.f, a3 = 0.f;
        #pragma unroll
        for (int it = 0; it < 8; it += 4) {
            float4 w0 = wr[lane + (it + 0) * 32];
            float4 w1 = wr[lane + (it + 1) * 32];
            float4 w2 = wr[lane + (it + 2) * 32];
            float4 w3 = wr[lane + (it + 3) * 32];
            float4 p0 = zs4[lane + (it + 0) * 32];
            float4 p1 = zs4[lane + (it + 1) * 32];
            float4 p2 = zs4[lane + (it + 2) * 32];
            float4 p3 = zs4[lane + (it + 3) * 32];
            a0 += w0.x * p0.x + w0.y * p0.y + w0.z * p0.z + w0.w * p0.w;
            a1 += w1.x * p1.x + w1.y * p1.y + w1.z * p1.z + w1.w * p1.w;
            a2 += w2.x * p2.x + w2.y * p2.y + w2.z * p2.z + w2.w * p2.w;
            a3 += w3.x * p3.x + w3.y * p3.y + w3.z * p3.z + w3.w * p3.w;
        }
        float dot = (a0 + a1) + (a2 + a3);

        #pragma unroll
        for (int off = 16; off; off >>= 1)
            dot += __shfl_xor_sync(0xffffffffu, dot, off);

        // ~row in low bits: ties resolve to SMALLEST row (jnp.argmax semantics).
        unsigned long long p =
            ((unsigned long long)float_key(dot) << 32) |
            (unsigned long long)(0xFFFFFFFFu - (unsigned)row);
        if (p > best) best = p;
    }

    // One value per warp -> smem max -> slot store -> release-count.
    if (lane == 0) red64[wwid] = best;
    __syncthreads();
    if (tid == 0) {
        unsigned long long v = red64[0];
        #pragma unroll
        for (int i = 1; i < ARG_THREADS / 32; i++)
            if (red64[i] > v) v = red64[i];
        g_block_best[blockIdx.x - 1] = v;
        __threadfence();                      // release the slot store
        atomicAdd(&g_done_count, 1u);
    }
}

extern "C" void kernel_launch(void* const* d_in, const int* in_sizes, int n_in,
                              void* d_out, int out_size) {
    const float* z = (const float*)d_in[0];
    const float* W = (const float*)d_in[1];
    if (n_in >= 2 && in_sizes[0] != VQ_DIM && in_sizes[1] == VQ_DIM) {
        z = (const float*)d_in[1];
        W = (const float*)d_in[0];
    }
    vq_kernel<<<ARG_BLOCKS + 1, ARG_THREADS>>>(z, W, (float*)d_out, out_size);
}

// round 10
// speedup vs baseline: 1.0703x; 1.0703x over previous
#include <cuda_runtime.h>

// VectorQuantizer: argmax_k ( W[k] . z ), emit W[argmax], index, commit loss.
// W: 131072 x 1024 f32 (512 MiB) -> HBM wall ~7.4 TB/s.
// Composition of the two best measured halves:
//   - R3 argmax (fastest streaming): 592 blocks, (256,4), 8-deep __ldcs batch,
//     slot stores (no atomics, no init kernel).
//   - R7 finalize (cheapest epilogue): PDL early-launch, z-prefetch before
//     griddepcontrol.wait, 512-thread single-pass scan + epilogue.
// Fusion is banned: 3x measured that epilogue code in the streaming kernel
// costs more in regs/occupancy than a second launch costs in overhead.

#define VQ_DIM   1024
#define VQ_ROWS  131072
#define ARG_CTAS_PER_SM 4
#define ARG_BLOCKS  592          // 148 SMs x 4 CTAs -> single persistent wave
#define ARG_THREADS 256
#define N_WARPS_TOT (ARG_BLOCKS * ARG_THREADS / 32)
#define FIN_THREADS 512

// Per-block packed (float_key(dot) << 32 | ~row). Overwritten every launch.
__device__ unsigned long long g_block_best[ARG_BLOCKS];

// Monotonic float -> uint key: preserves ordering for all finite floats.
__device__ __forceinline__ unsigned float_key(float f) {
    unsigned u = __float_as_uint(f);
    return (u & 0x80000000u) ? ~u : (u | 0x80000000u);
}

__global__ __launch_bounds__(ARG_THREADS, ARG_CTAS_PER_SM)  // 32 warps/SM
void vq_argmax_kernel(const float* __restrict__ z, const float* __restrict__ W) {
    __shared__ float zs[VQ_DIM];
    __shared__ unsigned long long red64[ARG_THREADS / 32];

    const int tid  = threadIdx.x;
    const int lane = tid & 31;
    const int wwid = tid >> 5;

    // Stage z into shared (4 KB), vectorized.
    const float4* z4 = (const float4*)z;
    float4* zs4 = (float4*)zs;
    for (int i = tid; i < VQ_DIM / 4; i += ARG_THREADS)
        zs4[i] = z4[i];
    __syncthreads();

    // Let the finalize grid launch now: it prefetches z during our stream and
    // its griddepcontrol.wait releases the moment this grid retires.
    if (tid == 0)
        asm volatile("griddepcontrol.launch_dependents;");

    const int gwarp = (blockIdx.x * ARG_THREADS + tid) >> 5;

    unsigned long long best = 0ULL;

    for (int row = gwarp; row < VQ_ROWS; row += N_WARPS_TOT) {
        const float4* wr = (const float4*)(W + (size_t)row * VQ_DIM);
        // All 8 LDG.128s issued up front (max per-warp MLP), streaming hint.
        float4 w0 = __ldcs(wr + lane +   0);
        float4 w1 = __ldcs(wr + lane +  32);
        float4 w2 = __ldcs(wr + lane +  64);
        float4 w3 = __ldcs(wr + lane +  96);
        float4 w4 = __ldcs(wr + lane + 128);
        float4 w5 = __ldcs(wr + lane + 160);
        float4 w6 = __ldcs(wr + lane + 192);
        float4 w7 = __ldcs(wr + lane + 224);
        float a0, a1, a2, a3;
        { float4 p = zs4[lane +   0]; a0  = w0.x*p.x + w0.y*p.y + w0.z*p.z + w0.w*p.w; }
        { float4 p = zs4[lane +  32]; a1  = w1.x*p.x + w1.y*p.y + w1.z*p.z + w1.w*p.w; }
        { float4 p = zs4[lane +  64]; a2  = w2.x*p.x + w2.y*p.y + w2.z*p.z + w2.w*p.w; }
        { float4 p = zs4[lane +  96]; a3  = w3.x*p.x + w3.y*p.y + w3.z*p.z + w3.w*p.w; }
        { float4 p = zs4[lane + 128]; a0 += w4.x*p.x + w4.y*p.y + w4.z*p.z + w4.w*p.w; }
        { float4 p = zs4[lane + 160]; a1 += w5.x*p.x + w5.y*p.y + w5.z*p.z + w5.w*p.w; }
        { float4 p = zs4[lane + 192]; a2 += w6.x*p.x + w6.y*p.y + w6.z*p.z + w6.w*p.w; }
        { float4 p = zs4[lane + 224]; a3 += w7.x*p.x + w7.y*p.y + w7.z*p.z + w7.w*p.w; }
        float dot = (a0 + a1) + (a2 + a3);

        #pragma unroll
        for (int off = 16; off; off >>= 1)
            dot += __shfl_xor_sync(0xffffffffu, dot, off);

        // ~row in low bits: ties resolve to SMALLEST row (jnp.argmax semantics).
        unsigned long long p =
            ((unsigned long long)float_key(dot) << 32) |
            (unsigned long long)(0xFFFFFFFFu - (unsigned)row);
        if (p > best) best = p;
    }

    // One value per warp -> 8-entry smem max -> slot store (no atomics).
    if (lane == 0) red64[wwid] = best;
    __syncthreads();
    if (tid == 0) {
        unsigned long long v = red64[0];
        #pragma unroll
        for (int i = 1; i < ARG_THREADS / 32; i++)
            if (red64[i] > v) v = red64[i];
        g_block_best[blockIdx.x] = v;
    }
}

__global__ __launch_bounds__(FIN_THREADS)
void vq_finalize_kernel(const float* __restrict__ z,
                        const float* __restrict__ W,
                        float* __restrict__ out, int out_size) {
    __shared__ unsigned long long red64[FIN_THREADS / 32];
    __shared__ float redf[FIN_THREADS / 32];
    const int tid  = threadIdx.x;
    const int lane = tid & 31;
    const int wwid = tid >> 5;

    // Prefetch z (independent of the primary) BEFORE the PDL wait so the
    // DRAM latency overlaps the argmax stream/drain.
    float zv0 = z[tid];
    float zv1 = z[tid + FIN_THREADS];

    asm volatile("griddepcontrol.wait;" ::: "memory");

    // Scan the 592 slots (<=2 per thread, L2-hot).
    unsigned long long b = g_block_best[tid < ARG_BLOCKS ? tid : 0];
    if (tid + FIN_THREADS < ARG_BLOCKS) {
        unsigned long long v = g_block_best[tid + FIN_THREADS];
        if (v > b) b = v;
    }
    #pragma unroll
    for (int off = 16; off; off >>= 1) {
        unsigned long long o = __shfl_xor_sync(0xffffffffu, b, off);
        if (o > b) b = o;
    }
    if (lane == 0) red64[wwid] = b;
    __syncthreads();
    if (tid == 0) {
        unsigned long long v = red64[0];
        #pragma unroll
        for (int i = 1; i < FIN_THREADS / 32; i++)
            if (red64[i] > v) v = red64[i];
        red64[0] = v;
    }
    __syncthreads();
    const unsigned row = 0xFFFFFFFFu - (unsigned)(red64[0] & 0xFFFFFFFFull);
    const float* q = W + (size_t)row * VQ_DIM;

    // Copy winning row + commitment loss. 2 elems/thread.
    float q0 = q[tid];
    float q1 = q[tid + FIN_THREADS];
    if (tid < out_size) out[tid] = q0;
    if (tid + FIN_THREADS < out_size) out[tid + FIN_THREADS] = q1;
    float d0 = zv0 - q0, d1 = zv1 - q1;
    float s = d0 * d0 + d1 * d1;
    #pragma unroll
    for (int off = 16; off; off >>= 1)
        s += __shfl_xor_sync(0xffffffffu, s, off);
    if (lane == 0) redf[wwid] = s;
    __syncthreads();
    if (tid == 0) {
        float t = 0.f;
        #pragma unroll
        for (int i = 0; i < FIN_THREADS / 32; i++) t += redf[i];
        if (out_size >= VQ_DIM + 1) out[VQ_DIM]     = (float)row;
        if (out_size >= VQ_DIM + 2) out[VQ_DIM + 1] = 0.25f * t / (float)VQ_DIM;
    }
}

extern "C" void kernel_launch(void* const* d_in, const int* in_sizes, int n_in,
                              void* d_out, int out_size) {
    const float* z = (const float*)d_in[0];
    const float* W = (const float*)d_in[1];
    if (n_in >= 2 && in_sizes[0] != VQ_DIM && in_sizes[1] == VQ_DIM) {
        z = (const float*)d_in[1];
        W = (const float*)d_in[0];
    }
    float* out = (float*)d_out;

    cudaLaunchConfig_t cfg1 = {};
    cfg1.gridDim  = dim3(ARG_BLOCKS);
    cfg1.blockDim = dim3(ARG_THREADS);
    cudaLaunchKernelEx(&cfg1, vq_argmax_kernel, z, W);

    cudaLaunchConfig_t cfg2 = {};
    cfg2.gridDim  = dim3(1);
    cfg2.blockDim = dim3(FIN_THREADS);
    cudaLaunchAttribute attr;
    attr.id = cudaLaunchAttributeProgrammaticStreamSerialization;
    attr.val.programmaticStreamSerializationAllowed = 1;
    cfg2.attrs = &attr;
    cfg2.numAttrs = 1;
    cudaLaunchKernelEx(&cfg2, vq_finalize_kernel, z, W, out, out_size);
}